// round 10
// baseline (speedup 1.0000x reference)
#include <cuda_runtime.h>

// ---------------------------------------------------------------------------
// GCN 2-layer forward. CSR aggregation + f32x2 GEMM1 (v2: crossbar-relieved)
//   h1 = x @ W1                              [N,128]   (FFMA2, 128x128 tiles)
//   hid = relu(A_norm @ h1 + b1)  (registers/smem only)
//   h2 = hid @ W2                            [N,16]    (fused into gather1)
//   out = log_softmax(A_norm @ h2 + b2)      [N,16]    (CSR gather)
// edge_index is int32 (JAX x64-disabled truncates the requested int64).
// CSR build forked onto a side stream, overlapped with GEMM1.
// ---------------------------------------------------------------------------

#define NMAX 50000
#define EMAX 800000
typedef unsigned long long ull;

__device__ int   g_indeg [NMAX];
__device__ int   g_cursor[NMAX];
__device__ int   g_rowptr[NMAX + 1];
__device__ int   g_scan  [NMAX];
__device__ int   g_bsum  [256];
__device__ int   g_boff  [256];
__device__ float g_dinv  [NMAX];
__device__ __align__(16) ull   g_emeta[EMAX];        // hi: norm bits, lo: src
__device__ __align__(16) float g_h1   [NMAX * 128];
__device__ __align__(16) float g_h2   [NMAX * 16];

// ---------------- f32x2 helpers --------------------------------------------

__device__ __forceinline__ void fma2(ull& acc, ull a, ull b) {
    asm("fma.rn.f32x2 %0, %1, %2, %0;" : "+l"(acc) : "l"(a), "l"(b));
}
__device__ __forceinline__ ull dup2(float w) {
    ull d; unsigned u = __float_as_uint(w);
    asm("mov.b64 %0, {%1, %1};" : "=l"(d) : "r"(u));
    return d;
}
__device__ __forceinline__ ull pack2(float lo, float hi) {
    ull d;
    asm("mov.b64 %0, {%1, %2};" : "=l"(d) : "r"(__float_as_uint(lo)), "r"(__float_as_uint(hi)));
    return d;
}
__device__ __forceinline__ float f2lo(ull v) { return __uint_as_float((unsigned)v); }
__device__ __forceinline__ float f2hi(ull v) { return __uint_as_float((unsigned)(v >> 32)); }

// ---------------- CSR build ------------------------------------------------

__global__ void k_init(int n) {
    int i = blockIdx.x * blockDim.x + threadIdx.x;
    if (i < n) { g_indeg[i] = 0; g_cursor[i] = 0; }
}

__global__ void k_deg_count(const int* __restrict__ dst, int E) {
    int e = blockIdx.x * blockDim.x + threadIdx.x;
    if (e < E) atomicAdd(&g_indeg[dst[e]], 1);
}

// inclusive scan within 256-blocks (warp shuffles)
__global__ void k_scan1(int n) {
    __shared__ int wsum[8];
    int t = threadIdx.x, i = blockIdx.x * 256 + t;
    int lane = t & 31, w = t >> 5;
    int x = (i < n) ? g_indeg[i] : 0;
#pragma unroll
    for (int o = 1; o < 32; o <<= 1) {
        int y = __shfl_up_sync(0xffffffffu, x, o);
        if (lane >= o) x += y;
    }
    if (lane == 31) wsum[w] = x;
    __syncthreads();
    if (w == 0) {
        int s = (lane < 8) ? wsum[lane] : 0;
#pragma unroll
        for (int o = 1; o < 8; o <<= 1) {
            int y = __shfl_up_sync(0xffffffffu, s, o);
            if (lane >= o) s += y;
        }
        if (lane < 8) wsum[lane] = s;
    }
    __syncthreads();
    if (w > 0) x += wsum[w - 1];
    if (i < n) g_scan[i] = x;
    if (t == 255) g_bsum[blockIdx.x] = x;
}

__global__ void k_scan2(int nb) {
    __shared__ int wsum[8];
    int t = threadIdx.x;
    int lane = t & 31, w = t >> 5;
    int v = (t < nb) ? g_bsum[t] : 0;
    int x = v;
#pragma unroll
    for (int o = 1; o < 32; o <<= 1) {
        int y = __shfl_up_sync(0xffffffffu, x, o);
        if (lane >= o) x += y;
    }
    if (lane == 31) wsum[w] = x;
    __syncthreads();
    if (w == 0) {
        int s = (lane < 8) ? wsum[lane] : 0;
#pragma unroll
        for (int o = 1; o < 8; o <<= 1) {
            int y = __shfl_up_sync(0xffffffffu, s, o);
            if (lane >= o) s += y;
        }
        if (lane < 8) wsum[lane] = s;
    }
    __syncthreads();
    if (w > 0) x += wsum[w - 1];
    g_boff[t] = x - v;   // exclusive
}

__global__ void k_scan3(int n) {     // rowptr + dinv
    int i = blockIdx.x * blockDim.x + threadIdx.x;
    if (i >= n) return;
    int deg = g_indeg[i];
    int off = g_boff[i >> 8];
    g_rowptr[i] = g_scan[i] - deg + off;
    if (i == n - 1) g_rowptr[n] = g_scan[i] + off;
    g_dinv[i] = rsqrtf((float)(deg + 1));
}

__global__ void k_fill(const int* __restrict__ src, const int* __restrict__ dst, int E) {
    int e = blockIdx.x * blockDim.x + threadIdx.x;
    if (e >= E) return;
    int s = src[e], d = dst[e];
    int pos = g_rowptr[d] + atomicAdd(&g_cursor[d], 1);
    float nm = g_dinv[s] * g_dinv[d];
    g_emeta[pos] = ((ull)__float_as_uint(nm) << 32) | (unsigned)s;
}

// ---------------- GEMM1 v2: h1 = x @ W1  (K=256, 128 cols) -----------------
// 128x128 tile, 256 threads, 8 rows x 8 cols per thread, K-chunks of 32.
// X packed as row-pair f32x2 ulls (swizzled rp ^ (kk>>2), conflict-free STS,
// broadcast LDS). W packed as (w,w) dup ulls, swizzled so the 16-lane
// LDS.128 hits the 2-phase crossbar minimum. Inner: 32 FFMA2, 8 LDS per kk.

__global__ void __launch_bounds__(256) k_gemm1(const float* __restrict__ X,
                                               const float* __restrict__ W,
                                               int n) {
    __shared__ ull XsP[32][64];     // [kk][rp^(kk>>2)] = (row2rp, row2rp+1)  16KB
    __shared__ ull WsP[32][128];    // [kk][8*cg + 2*(i^((cg>>1)&3)) + b]     32KB
    const int tid = threadIdx.x;
    const int cg  = tid & 15;       // cols 8*cg .. +7
    const int rg  = tid >> 4;       // row pairs rg*4 .. +3 (rows rg*8 .. +7)
    const int swc = (cg >> 1) & 3;
    const int row0 = blockIdx.x * 128;
    const int rpb  = rg << 2;

    ull acc[4][8];
#pragma unroll
    for (int rp = 0; rp < 4; rp++)
#pragma unroll
        for (int c = 0; c < 8; c++) acc[rp][c] = 0ull;

    for (int ch = 0; ch < 8; ch++) {
        const int k0 = ch << 5;
        // ---- stage X: 64 row-pairs x 32 k, packed ----
#pragma unroll
        for (int i = tid; i < 512; i += 256) {
            int rp = i >> 3, f4 = i & 7;
            int r0 = row0 + 2 * rp;
            float4 a = make_float4(0.f, 0.f, 0.f, 0.f);
            float4 b = make_float4(0.f, 0.f, 0.f, 0.f);
            if (r0 < n)     a = *(const float4*)(X + (size_t)r0 * 256 + k0 + (f4 << 2));
            if (r0 + 1 < n) b = *(const float4*)(X + (size_t)(r0 + 1) * 256 + k0 + (f4 << 2));
            int sr = rp ^ f4;                       // swizzled rp (kk>>2 == f4)
            XsP[(f4 << 2) + 0][sr] = pack2(a.x, b.x);
            XsP[(f4 << 2) + 1][sr] = pack2(a.y, b.y);
            XsP[(f4 << 2) + 2][sr] = pack2(a.z, b.z);
            XsP[(f4 << 2) + 3][sr] = pack2(a.w, b.w);
        }
        // ---- stage W: 32 k x 128 cols, dup-packed + swizzled ----
#pragma unroll
        for (int f = tid; f < 1024; f += 256) {
            int kk = f >> 5, c0 = (f & 31) << 2;
            float4 w = *(const float4*)(W + (size_t)(k0 + kk) * 128 + c0);
            float ws[4] = {w.x, w.y, w.z, w.w};
#pragma unroll
            for (int j = 0; j < 4; j++) {
                int c   = c0 + j;
                int cgd = c >> 3, t = c & 7;
                int slot = (cgd << 3) + (((t >> 1) ^ ((cgd >> 1) & 3)) << 1) + (t & 1);
                WsP[kk][slot] = dup2(ws[j]);
            }
        }
        __syncthreads();

#pragma unroll 8
        for (int kk = 0; kk < 32; kk++) {
            const int xsw = kk >> 2;
            ull x0 = XsP[kk][(rpb + 0) ^ xsw];
            ull x1 = XsP[kk][(rpb + 1) ^ xsw];
            ull x2 = XsP[kk][(rpb + 2) ^ xsw];
            ull x3 = XsP[kk][(rpb + 3) ^ xsw];
            ull wd[8];
#pragma unroll
            for (int i = 0; i < 4; i++) {
                // pair i lives at slot 8*cg + 2*(i^swc); LDS.128 returns cols (2i, 2i+1)
                const ull* p = &WsP[kk][(cg << 3) + ((i ^ swc) << 1)];
                ull2w: ;
                ull lo = p[0], hi = p[1];
                wd[2 * i]     = lo;
                wd[2 * i + 1] = hi;
            }
#pragma unroll
            for (int c = 0; c < 8; c++) {
                fma2(acc[0][c], x0, wd[c]);
                fma2(acc[1][c], x1, wd[c]);
                fma2(acc[2][c], x2, wd[c]);
                fma2(acc[3][c], x3, wd[c]);
            }
        }
        __syncthreads();
    }

    // ---- epilogue ----
#pragma unroll
    for (int rp = 0; rp < 4; rp++) {
        int r0 = row0 + (rg << 3) + (rp << 1);
        if (r0 < n) {
            *(float4*)(g_h1 + (size_t)r0 * 128 + (cg << 3)) =
                make_float4(f2lo(acc[rp][0]), f2lo(acc[rp][1]), f2lo(acc[rp][2]), f2lo(acc[rp][3]));
            *(float4*)(g_h1 + (size_t)r0 * 128 + (cg << 3) + 4) =
                make_float4(f2lo(acc[rp][4]), f2lo(acc[rp][5]), f2lo(acc[rp][6]), f2lo(acc[rp][7]));
        }
        if (r0 + 1 < n) {
            *(float4*)(g_h1 + (size_t)(r0 + 1) * 128 + (cg << 3)) =
                make_float4(f2hi(acc[rp][0]), f2hi(acc[rp][1]), f2hi(acc[rp][2]), f2hi(acc[rp][3]));
            *(float4*)(g_h1 + (size_t)(r0 + 1) * 128 + (cg << 3) + 4) =
                make_float4(f2hi(acc[rp][4]), f2hi(acc[rp][5]), f2hi(acc[rp][6]), f2hi(acc[rp][7]));
        }
    }
}

// ---------------- fused gather1 + GEMM2 (warp per node) --------------------

__global__ void __launch_bounds__(256) k_gather1_gemm2(const float* __restrict__ b1,
                                                       const float* __restrict__ W2,
                                                       int n) {
    __shared__ float W2s[16][132];        // W2s[j][k] = W2[k][j] (transposed, padded)
    __shared__ float hidS[8][128];        // per-warp hid row
    const int tid  = threadIdx.x;
    const int w    = tid >> 5;
    const int lane = tid & 31;

#pragma unroll
    for (int i = tid; i < 2048; i += 256) {
        int k = i >> 4, j = i & 15;
        W2s[j][k] = W2[k * 16 + j];
    }
    __syncthreads();

    int node = blockIdx.x * 8 + w;
    if (node >= n) return;
    int c = lane << 2;

    float di  = g_dinv[node];
    float di2 = di * di;
    float4 h  = *(const float4*)(g_h1 + (size_t)node * 128 + c);
    float4 a;
    a.x = di2 * h.x; a.y = di2 * h.y; a.z = di2 * h.z; a.w = di2 * h.w;

    int beg = g_rowptr[node], end = g_rowptr[node + 1];
    if (beg < end) {
        ull m0 = g_emeta[beg];
        float4 v0 = *(const float4*)(g_h1 + (size_t)(unsigned)m0 * 128 + c);
        for (int e = beg + 1; e < end; e++) {
            ull m1 = g_emeta[e];
            float4 v1 = *(const float4*)(g_h1 + (size_t)(unsigned)m1 * 128 + c);
            float nm = __uint_as_float((unsigned)(m0 >> 32));
            a.x += nm * v0.x; a.y += nm * v0.y; a.z += nm * v0.z; a.w += nm * v0.w;
            m0 = m1; v0 = v1;
        }
        float nm = __uint_as_float((unsigned)(m0 >> 32));
        a.x += nm * v0.x; a.y += nm * v0.y; a.z += nm * v0.z; a.w += nm * v0.w;
    }
    float4 b = *(const float4*)(b1 + c);
    float4 o;
    o.x = fmaxf(a.x + b.x, 0.f);
    o.y = fmaxf(a.y + b.y, 0.f);
    o.z = fmaxf(a.z + b.z, 0.f);
    o.w = fmaxf(a.w + b.w, 0.f);

    *(float4*)&hidS[w][c] = o;
    __syncwarp();

    const int j  = lane & 15;
    const int k0 = (lane >> 4) << 6;
    float acc = 0.f;
#pragma unroll
    for (int kk = 0; kk < 64; kk += 4) {
        float4 hv = *(float4*)&hidS[w][k0 + kk];
        float4 wv = *(float4*)&W2s[j][k0 + kk];
        acc += hv.x * wv.x + hv.y * wv.y + hv.z * wv.z + hv.w * wv.w;
    }
    acc += __shfl_down_sync(0xffffffffu, acc, 16);
    if (lane < 16) g_h2[(size_t)node * 16 + j] = acc;
}

// ---------------- gather layer 2 + log_softmax (4 lanes per node) ----------

__global__ void __launch_bounds__(256) k_gather2(const float* __restrict__ b2,
                                                 float* __restrict__ out, int n) {
    int g    = blockIdx.x * 256 + threadIdx.x;
    int node = g >> 2, q = g & 3;
    if (node >= n) return;
    int c = q << 2;

    float di  = g_dinv[node];
    float di2 = di * di;
    float4 h  = *(const float4*)(g_h2 + (size_t)node * 16 + c);
    float4 a;
    a.x = di2 * h.x; a.y = di2 * h.y; a.z = di2 * h.z; a.w = di2 * h.w;

    int beg = g_rowptr[node], end = g_rowptr[node + 1];
    if (beg < end) {
        ull m0 = g_emeta[beg];
        float4 v0 = *(const float4*)(g_h2 + (size_t)(unsigned)m0 * 16 + c);
        for (int e = beg + 1; e < end; e++) {
            ull m1 = g_emeta[e];
            float4 v1 = *(const float4*)(g_h2 + (size_t)(unsigned)m1 * 16 + c);
            float nm = __uint_as_float((unsigned)(m0 >> 32));
            a.x += nm * v0.x; a.y += nm * v0.y; a.z += nm * v0.z; a.w += nm * v0.w;
            m0 = m1; v0 = v1;
        }
        float nm = __uint_as_float((unsigned)(m0 >> 32));
        a.x += nm * v0.x; a.y += nm * v0.y; a.z += nm * v0.z; a.w += nm * v0.w;
    }
    float4 b = *(const float4*)(b2 + c);
    a.x += b.x; a.y += b.y; a.z += b.z; a.w += b.w;

    float m4 = fmaxf(fmaxf(a.x, a.y), fmaxf(a.z, a.w));
    m4 = fmaxf(m4, __shfl_xor_sync(0xffffffffu, m4, 1, 4));
    m4 = fmaxf(m4, __shfl_xor_sync(0xffffffffu, m4, 2, 4));
    float s4 = expf(a.x - m4) + expf(a.y - m4) + expf(a.z - m4) + expf(a.w - m4);
    s4 += __shfl_xor_sync(0xffffffffu, s4, 1, 4);
    s4 += __shfl_xor_sync(0xffffffffu, s4, 2, 4);
    float lse = m4 + logf(s4);

    float4 o;
    o.x = a.x - lse; o.y = a.y - lse; o.z = a.z - lse; o.w = a.w - lse;
    *(float4*)(out + (size_t)node * 16 + c) = o;
}

// ---------------------------------------------------------------------------

extern "C" void kernel_launch(void* const* d_in, const int* in_sizes, int n_in,
                              void* d_out, int out_size) {
    const float* x  = (const float*)d_in[0];
    const int*   ei = (const int*)d_in[1];          // int32 (JAX truncation)
    const float* W1 = (const float*)d_in[2];
    const float* b1 = (const float*)d_in[3];
    const float* W2 = (const float*)d_in[4];
    const float* b2 = (const float*)d_in[5];
    float*       out = (float*)d_out;

    const int n = in_sizes[0] / 256;
    const int E = in_sizes[1] / 2;
    const int* src = ei;
    const int* dst = ei + E;
    const int nb = (n + 255) / 256;

    const int T = 256;
    dim3 b(T);

    static cudaStream_t sCsr = nullptr;
    static cudaEvent_t  eFork = nullptr, eJoin = nullptr;
    if (!sCsr) {
        cudaStreamCreateWithFlags(&sCsr, cudaStreamNonBlocking);
        cudaEventCreateWithFlags(&eFork, cudaEventDisableTiming);
        cudaEventCreateWithFlags(&eJoin, cudaEventDisableTiming);
    }

    // fork: CSR build on side stream, GEMM1 on main stream.
    // (gemm1 launched mid-chain so ncu's fixed skip window catches it.)
    cudaEventRecord(eFork, 0);
    cudaStreamWaitEvent(sCsr, eFork, 0);

    k_init     <<<(n + T - 1) / T, b, 0, sCsr>>>(n);
    k_deg_count<<<(E + T - 1) / T, b, 0, sCsr>>>(dst, E);
    k_scan1    <<<nb, b, 0, sCsr>>>(n);

    k_gemm1<<<(n + 127) / 128, b>>>(x, W1, n);

    k_scan2    <<<1, b, 0, sCsr>>>(nb);
    k_scan3    <<<nb, b, 0, sCsr>>>(n);
    k_fill     <<<(E + T - 1) / T, b, 0, sCsr>>>(src, dst, E);
    cudaEventRecord(eJoin, sCsr);

    // join, then the dependent chain
    cudaStreamWaitEvent(0, eJoin, 0);
    k_gather1_gemm2<<<(n + 7) / 8, b>>>(b1, W2, n);
    k_gather2<<<(n * 4 + T - 1) / T, b>>>(b2, out, n);
}